// round 14
// baseline (speedup 1.0000x reference)
#include <cuda_runtime.h>
#include <cuda_fp16.h>
#include <math.h>

#define NSEQ 2048
#define NTOT 4096
#define DIMV 1024
#define HH   16
#define KVHH 4

// ---------------- scratch ---------------------------------------------------
__device__ __half g_sx[NSEQ * DIMV];        // rmsnorm out, perm'd k-dim
__device__ __half g_sa[NSEQ * DIMV];
__device__ float  g_qraw_x[NSEQ * 1024];
__device__ float  g_qraw_a[NSEQ * 1024];
__device__ float  g_kvraw_x[NSEQ * 512];
__device__ float  g_kvraw_a[NSEQ * 512];
__device__ __half g_q[HH * NTOT * 64];      // pair-packed frag layout
__device__ __half g_k[KVHH * NTOT * 64];    // pair-packed frag layout
__device__ __half g_v[KVHH * NTOT * 64];    // pair-packed octrow layout
__device__ __half g_o[NTOT * DIMV];         // attention out, perm'd k-dim
__device__ float  g_tabc[NSEQ * 32];
__device__ float  g_tabs[NSEQ * 32];
// weights in fp16 octrow layout
__device__ __half g_wq_x[1024 * 1024];
__device__ __half g_wkv_x[1024 * 512];
__device__ __half g_wq_a[1024 * 1024];
__device__ __half g_wkv_a[1024 * 512];
__device__ __half g_wout_x[1024 * 1024];
__device__ __half g_wout_a[1024 * 1024];

// ---------------- helpers ----------------------------------------------------
__device__ __host__ __forceinline__ int perm16(int e) {
    return ((e & 7) >> 1) * 4 + ((e >> 3) << 1) + (e & 1);
}
// pair-packed Q/K row position
__device__ __forceinline__ int qk_pos(int d) {
    int ks = d >> 4, e = d & 15;
    return (ks >> 1) * 32 + ((e & 7) >> 1) * 8 + (ks & 1) * 4
         + ((e >> 3) << 1) + (e & 1);
}
__device__ __forceinline__ unsigned ex2h2(__half2 h) {
    unsigned u = *(unsigned*)&h, y;
    asm("ex2.approx.f16x2 %0, %1;" : "=r"(y) : "r"(u));
    return y;
}
__device__ __forceinline__ void mma16(float* c, const unsigned* a, unsigned b0, unsigned b1) {
    asm volatile(
        "mma.sync.aligned.m16n8k16.row.col.f32.f16.f16.f32 "
        "{%0,%1,%2,%3},{%4,%5,%6,%7},{%8,%9},{%0,%1,%2,%3};"
        : "+f"(c[0]), "+f"(c[1]), "+f"(c[2]), "+f"(c[3])
        : "r"(a[0]), "r"(a[1]), "r"(a[2]), "r"(a[3]), "r"(b0), "r"(b1));
}
__device__ __forceinline__ void cpa(void* dst, const void* src) {
    unsigned d = (unsigned)__cvta_generic_to_shared(dst);
    asm volatile("cp.async.cg.shared.global [%0], [%1], 16;" :: "r"(d), "l"(src));
}
#define CP_COMMIT() asm volatile("cp.async.commit_group;" ::)
#define CP_WAIT0()  asm volatile("cp.async.wait_group 0;" ::)
#define CP_WAIT1()  asm volatile("cp.async.wait_group 1;" ::)

// ---------------- prep: weights -> fp16 octrow + rope table ------------------
__global__ void prep_kernel(const float* __restrict__ wqx_s, const float* __restrict__ wkvx_s,
                            const float* __restrict__ wqa_s, const float* __restrict__ wkva_s,
                            const float* __restrict__ woutx_s, const float* __restrict__ wouta_s) {
    int i = blockIdx.x * 256 + threadIdx.x;
    const int I1 = 262144, I2 = I1 + 131072, I3 = I2 + 262144;
    const int I4 = I3 + 131072, I5 = I4 + 262144, I6 = I5 + 262144;  // 1310720
    if (i < I6) {
        const float* src; __half* dst; int off, N;
        if (i < I1)      { src = wqx_s;   dst = g_wq_x;   off = i;      N = 1024; }
        else if (i < I2) { src = wkvx_s;  dst = g_wkv_x;  off = i - I1; N = 512; }
        else if (i < I3) { src = wqa_s;   dst = g_wq_a;   off = i - I2; N = 1024; }
        else if (i < I4) { src = wkva_s;  dst = g_wkv_a;  off = i - I3; N = 512; }
        else if (i < I5) { src = woutx_s; dst = g_wout_x; off = i - I4; N = 1024; }
        else             { src = wouta_s; dst = g_wout_a; off = i - I5; N = 1024; }
        int nh = N >> 1;
        int k = (off / nh) * 2, n = (off % nh) * 2;
        float2 r0 = *(const float2*)(src + (size_t)k * N + n);
        float2 r1 = *(const float2*)(src + (size_t)(k + 1) * N + n);
        int J = k >> 4, e = k & 15;
        int qr = (e & 7) >> 1, s = (e >> 3) << 1;   // e even
        size_t base = (size_t)J * 16 * N + (size_t)qr * 4 * N + (size_t)n * 4 + s;
        *(__half2*)(dst + base)     = __floats2half2_rn(r0.x, r1.x);
        *(__half2*)(dst + base + 4) = __floats2half2_rn(r0.y, r1.y);
    } else if (i < I6 + NSEQ * 32 / 2) {
        int j = (i - I6) * 2;
        #pragma unroll
        for (int u = 0; u < 2; u++) {
            int idx = j + u;
            int t = idx >> 5, fi = idx & 31;
            float invf = powf(10000.0f, -(float)fi * (1.0f / 32.0f));
            float ang = (2.0f * (float)t) * invf;
            float sn, cs;
            sincosf(ang, &sn, &cs);
            g_tabc[idx] = cs;
            g_tabs[idx] = sn;
        }
    }
}

// ---------------- RMSNorm -> fp16 perm'd output -------------------------------
__global__ void rmsnorm_kernel(const float* __restrict__ x0, const float* __restrict__ x1,
                               const float* __restrict__ g0, const float* __restrict__ g1,
                               __half* __restrict__ o0, __half* __restrict__ o1) {
    const float* x = blockIdx.y ? x1 : x0;
    const float* g = blockIdx.y ? g1 : g0;
    __half* out = blockIdx.y ? o1 : o0;
    int row = blockIdx.x;
    const float4* xr = (const float4*)(x + (size_t)row * DIMV);
    float4 v = xr[threadIdx.x];
    float ss = v.x * v.x + v.y * v.y + v.z * v.z + v.w * v.w;
    __shared__ float red[8];
    #pragma unroll
    for (int m = 16; m; m >>= 1) ss += __shfl_xor_sync(0xffffffffu, ss, m);
    if ((threadIdx.x & 31) == 0) red[threadIdx.x >> 5] = ss;
    __syncthreads();
    if (threadIdx.x < 8) {
        float t = red[threadIdx.x];
        #pragma unroll
        for (int m = 4; m; m >>= 1) t += __shfl_xor_sync(0xffu, t, m);
        if (threadIdx.x == 0) red[0] = t;
    }
    __syncthreads();
    float rs = rsqrtf(red[0] * (1.0f / (float)DIMV) + 1e-6f);
    float4 gv = ((const float4*)g)[threadIdx.x];
    int d0 = threadIdx.x * 4;
    int base = d0 & ~15, e0 = d0 & 15;
    __half* outrow = out + (size_t)row * DIMV + base;
    *(__half2*)(outrow + perm16(e0))     = __floats2half2_rn(v.x * rs * gv.x, v.y * rs * gv.y);
    *(__half2*)(outrow + perm16(e0 + 2)) = __floats2half2_rn(v.z * rs * gv.z, v.w * rs * gv.w);
}

// ---------------- fp16 GEMM: 128x128, 3-stage cp.async, 1 sync/iter ----------
#define GASTR 48
#define GBSTR 528
#define GSTAGE (128 * GASTR)
#define BSTAGE (8 * GBSTR)
__global__ void __launch_bounds__(256, 2) gemm_fp16(
    const __half* __restrict__ Az0, const __half* __restrict__ Az1,
    const __half* __restrict__ Bq0, const __half* __restrict__ Bq1,
    float* __restrict__ Cq0, float* __restrict__ Cq1, int N1,
    const __half* __restrict__ Bk0, const __half* __restrict__ Bk1,
    float* __restrict__ Ck0, float* __restrict__ Ck1, int N2,
    int split,
    const float* __restrict__ bias0, const float* __restrict__ bias1,
    int M, int K) {
    const __half* A = blockIdx.z ? Az1 : Az0;
    const __half* B;
    float* C;
    const float* bias = blockIdx.z ? bias1 : bias0;
    int N, n0;
    if ((int)blockIdx.x < split) {
        B = blockIdx.z ? Bq1 : Bq0; C = blockIdx.z ? Cq1 : Cq0;
        N = N1; n0 = blockIdx.x * 128;
    } else {
        B = blockIdx.z ? Bk1 : Bk0; C = blockIdx.z ? Ck1 : Ck0;
        N = N2; n0 = (blockIdx.x - split) * 128;
    }
    extern __shared__ __half smh[];
    __half* As = smh;                       // [3][128*48]
    __half* Bs = smh + 3 * GSTAGE;          // [3][8*528]
    int m0 = blockIdx.y * 128;
    int tid = threadIdx.x;
    int warp = tid >> 5, lane = tid & 31;
    int wm = warp >> 2, wn = warp & 3;
    int g = lane >> 2, qr = lane & 3;

    float acc[4][4][4];
    #pragma unroll
    for (int mt = 0; mt < 4; mt++)
        #pragma unroll
        for (int nt = 0; nt < 4; nt++)
            #pragma unroll
            for (int i = 0; i < 4; i++) acc[mt][nt][i] = 0.0f;

    auto stage = [&](int k0, int buf) {
        __half* ab = As + buf * GSTAGE;
        __half* bb = Bs + buf * BSTAGE;
        #pragma unroll
        for (int i = 0; i < 2; i++) {
            int f = tid + i * 256;
            int r = f >> 2, c = f & 3;
            cpa(ab + r * GASTR + c * 8, A + (size_t)(m0 + r) * K + k0 + c * 8);
        }
        #pragma unroll
        for (int i = 0; i < 2; i++) {
            int f = tid + i * 256;
            int orow = f >> 6, c = f & 63;
            int J = (k0 >> 4) + (orow >> 2);
            cpa(bb + orow * GBSTR + c * 8,
                B + ((size_t)J * 16 + (orow & 3) * 4) * N + (size_t)n0 * 4 + c * 8);
        }
    };

    int nk = K >> 5;                         // 32
    stage(0, 0);
    CP_COMMIT();
    stage(32, 1);
    CP_COMMIT();
    int bcur = 0, bnxt2 = 2;
    for (int it = 0; it < nk; it++) {
        CP_WAIT1();                          // stage it landed
        __syncthreads();                     // buffer (it-1)%3 free
        if (it + 2 < nk) {
            stage((it + 2) << 5, bnxt2);
            CP_COMMIT();
        }
        const __half* as = As + bcur * GSTAGE;
        const __half* bs = Bs + bcur * BSTAGE;
        #pragma unroll
        for (int ks = 0; ks < 2; ks++) {
            unsigned a[4][4], b[4][2];
            #pragma unroll
            for (int mt = 0; mt < 4; mt++) {
                int rb = wm * 64 + mt * 16;
                uint2 lo = *(const uint2*)(as + (rb + g) * GASTR + ks * 16 + qr * 4);
                uint2 hi = *(const uint2*)(as + (rb + g + 8) * GASTR + ks * 16 + qr * 4);
                a[mt][0] = lo.x; a[mt][1] = hi.x; a[mt][2] = lo.y; a[mt][3] = hi.y;
            }
            #pragma unroll
            for (int nt = 0; nt < 4; nt++) {
                uint2 bv = *(const uint2*)(bs + (ks * 4 + qr) * GBSTR + (wn * 32 + nt * 8 + g) * 4);
                b[nt][0] = bv.x; b[nt][1] = bv.y;
            }
            #pragma unroll
            for (int mt = 0; mt < 4; mt++)
                #pragma unroll
                for (int nt = 0; nt < 4; nt++)
                    mma16(acc[mt][nt], a[mt], b[nt][0], b[nt][1]);
        }
        bcur = (bcur == 2) ? 0 : bcur + 1;
        bnxt2 = (bnxt2 == 2) ? 0 : bnxt2 + 1;
    }

    #pragma unroll
    for (int mt = 0; mt < 4; mt++) {
        int row0 = m0 + wm * 64 + mt * 16 + g;
        #pragma unroll
        for (int nt = 0; nt < 4; nt++) {
            int col = n0 + wn * 32 + nt * 8 + qr * 2;
            float bx = 0.0f, by = 0.0f;
            if (bias) { float2 bb = *(const float2*)(bias + col); bx = bb.x; by = bb.y; }
            float2 lo = {acc[mt][nt][0] + bx, acc[mt][nt][1] + by};
            float2 hi = {acc[mt][nt][2] + bx, acc[mt][nt][3] + by};
            *(float2*)(C + (size_t)row0 * N + col) = lo;
            *(float2*)(C + (size_t)(row0 + 8) * N + col) = hi;
        }
    }
}

// ---------------- RoPE + scatter -> pair-packed fp16 layouts -----------------
__global__ void rope_scatter_kernel(const float* __restrict__ qraw_a, const float* __restrict__ qraw_x,
                                    const float* __restrict__ kvraw_a, const float* __restrict__ kvraw_x) {
    const float* qraw = blockIdx.y ? qraw_x : qraw_a;
    const float* kvraw = blockIdx.y ? kvraw_x : kvraw_a;
    int toff = blockIdx.y ? NSEQ : 0;
    int idx = blockIdx.x * 256 + threadIdx.x;
    if (idx >= NSEQ * 576) return;
    int t = idx / 576;
    int c = idx % 576;
    const float QSC = 0.015625f * 1.44269504088896f;  // 1/DH * log2(e)

    if (c < 320) {
        bool isQ = c < 256;
        int cc = isQ ? c : c - 256;
        int h = cc >> 4;
        int d = (cc & 15) * 2;        // d in [0,32), even
        const float* base = isQ ? (qraw + t * 1024 + h * 64)
                                : (kvraw + t * 512 + h * 64);
        float2 lo = *(const float2*)(base + d);
        float2 hi = *(const float2*)(base + d + 32);
        float c0 = g_tabc[t * 32 + d], c1 = g_tabc[t * 32 + d + 1];
        float s0 = g_tabs[t * 32 + d], s1 = g_tabs[t * 32 + d + 1];
        float lo0 = lo.x * c0 - hi.x * s0, lo1 = lo.y * c1 - hi.y * s1;
        float hi0 = hi.x * c0 + lo.x * s0, hi1 = hi.y * c1 + lo.y * s1;
        __half* dst;
        if (isQ) {
            lo0 *= QSC; lo1 *= QSC; hi0 *= QSC; hi1 *= QSC;
            dst = g_q + ((size_t)h * NTOT + toff + t) * 64;
        } else {
            dst = g_k + ((size_t)h * NTOT + toff + t) * 64;
        }
        *(__half2*)(dst + qk_pos(d))      = __floats2half2_rn(lo0, lo1);
        *(__half2*)(dst + qk_pos(d + 32)) = __floats2half2_rn(hi0, hi1);
    } else {
        int cc = c - 320;
        int kh = cc >> 6, d = cc & 63;
        int tj = toff + t;
        int r = tj & 63;
        int j = r >> 4, e = r & 15;
        int qrv = (e & 7) >> 1, sv = ((e >> 3) << 1) | (e & 1);
        int nt = d >> 3, gg = d & 7;
        size_t pos = (size_t)kh * NTOT * 64 + (size_t)(tj >> 6) * 4096
                   + (size_t)(j * 4 + qrv) * 256
                   + (nt >> 1) * 64 + gg * 8 + (nt & 1) * 4 + sv;
        g_v[pos] = __float2half_rn(kvraw[t * 512 + 256 + kh * 64 + d]);
    }
}

// ---------------- Flash attention: pair-packed LDS.128, staggered halves -----
#define AKSTR 96
#define AVSTR 272
__global__ void __launch_bounds__(256, 2) attn_tc_kernel(
    const __half* __restrict__ Q, const __half* __restrict__ K,
    const __half* __restrict__ V, __half* __restrict__ O) {
    extern __shared__ __half smh[];
    __half* Ks = smh;                        // [2][128*96]
    __half* Vs = smh + 2 * 128 * AKSTR;      // [2][32*272]

    int kh = blockIdx.y;
    int q0 = blockIdx.x * 32;
    int tid = threadIdx.x;
    int warp = tid >> 5, lane = tid & 31;
    int g = lane >> 2, qr = lane & 3;
    int hq = kh + (warp >> 1) * 4;
    int qrow0 = q0 + (warp & 1) * 16;

    const __half* Kg = K + (size_t)kh * NTOT * 64;
    const __half* Vg = V + (size_t)kh * NTOT * 64;

    auto stage = [&](int kt, int buf) {
        const __half* Kt = Kg + (size_t)kt * 8192;
        const __half* Vt = Vg + (size_t)kt * 8192;
        __half* kb = Ks + buf * 128 * AKSTR;
        __half* vb = Vs + buf * 32 * AVSTR;
        #pragma unroll
        for (int i = 0; i < 4; i++) {
            int f = tid + i * 256;
            int r = f >> 3, c = f & 7;
            cpa(kb + r * AKSTR + c * 8, Kt + r * 64 + c * 8);
        }
        #pragma unroll
        for (int i = 0; i < 4; i++) {
            int f = tid + i * 256;
            int orow = f >> 5, c = f & 31;
            cpa(vb + orow * AVSTR + c * 8, Vt + orow * 256 + c * 8);
        }
    };

    stage(0, 0);
    CP_COMMIT();

    unsigned qa[4][4];
    {
        const __half* Qg = Q + ((size_t)hq * NTOT + qrow0) * 64;
        #pragma unroll
        for (int p = 0; p < 2; p++) {
            uint4 Ug = *(const uint4*)(Qg + g * 64 + p * 32 + qr * 8);
            uint4 Uh = *(const uint4*)(Qg + (g + 8) * 64 + p * 32 + qr * 8);
            qa[2 * p][0] = Ug.x;     qa[2 * p][2] = Ug.y;
            qa[2 * p + 1][0] = Ug.z; qa[2 * p + 1][2] = Ug.w;
            qa[2 * p][1] = Uh.x;     qa[2 * p][3] = Uh.y;
            qa[2 * p + 1][1] = Uh.z; qa[2 * p + 1][3] = Uh.w;
        }
    }

    float o[8][4];
    #pragma unroll
    for (int nt = 0; nt < 8; nt++)
        #pragma unroll
        for (int i = 0; i < 4; i++) o[nt][i] = 0.0f;
    float lacc[4] = {0.0f, 0.0f, 0.0f, 0.0f};
    const unsigned ONES2 = 0x3C003C00u;
    const __half2 HCLAMP = __floats2half2_rn(15.0f, 15.0f);

    auto compute64 = [&](const __half* kb, const __half* vb) {
        float sacc[8][4];
        #pragma unroll
        for (int nt = 0; nt < 8; nt++) {
            #pragma unroll
            for (int i = 0; i < 4; i++) sacc[nt][i] = 0.0f;
            const __half* krow = kb + (nt * 8 + g) * AKSTR + qr * 8;
            #pragma unroll
            for (int p = 0; p < 2; p++) {
                uint4 kk = *(const uint4*)(krow + p * 32);
                mma16(sacc[nt], qa[2 * p],     kk.x, kk.y);
                mma16(sacc[nt], qa[2 * p + 1], kk.z, kk.w);
            }
        }
        #pragma unroll
        for (int j = 0; j < 4; j++) {
            unsigned pa[4];
            #pragma unroll
            for (int t = 0; t < 2; t++) {
                int nt = 2 * j + t;
                __half2 h0 = __floats2half2_rn(sacc[nt][0], sacc[nt][1]);
                __half2 h1 = __floats2half2_rn(sacc[nt][2], sacc[nt][3]);
                h0 = __hmin2(h0, HCLAMP);
                h1 = __hmin2(h1, HCLAMP);
                pa[2 * t]     = ex2h2(h0);
                pa[2 * t + 1] = ex2h2(h1);
            }
            mma16(lacc, pa, ONES2, ONES2);
            const __half* vrow = vb + (j * 4 + qr) * AVSTR + g * 8;
            #pragma unroll
            for (int nt2 = 0; nt2 < 4; nt2++) {
                uint4 vv = *(const uint4*)(vrow + nt2 * 64);
                mma16(o[2 * nt2], pa, vv.x, vv.y);
                mma16(o[2 * nt2 + 1], pa, vv.z, vv.w);
            }
        }
    };

    // stagger: warp-groups process the two 64-row halves in opposite order so
    // one group's softmax ALU phase overlaps the other's MMA phase per SMSP.
    bool fwd = (warp < 4);
    for (int kt = 0; kt < NTOT / 128; kt++) {
        CP_WAIT0();
        __syncthreads();
        if (kt + 1 < NTOT / 128) {
            stage(kt + 1, (kt + 1) & 1);
            CP_COMMIT();
        }
        const __half* kb = Ks + (kt & 1) * 128 * AKSTR;
        const __half* vb = Vs + (kt & 1) * 32 * AVSTR;
        if (fwd) {
            compute64(kb, vb);
            compute64(kb + 64 * AKSTR, vb + 16 * AVSTR);
        } else {
            compute64(kb + 64 * AKSTR, vb + 16 * AVSTR);
            compute64(kb, vb);
        }
    }

    float inv0 = 1.0f / lacc[0], inv1 = 1.0f / lacc[2];
    int t0 = qrow0 + g;
    __half* Ob = O + (size_t)t0 * DIMV + hq * 64;
    #pragma unroll
    for (int nt = 0; nt < 8; nt++) {
        int c = nt * 8 + qr * 2;
        int pos = (c & ~15) | perm16(c & 15);
        *(__half2*)(Ob + pos) = __floats2half2_rn(o[nt][0] * inv0, o[nt][1] * inv0);
        *(__half2*)(Ob + (size_t)8 * DIMV + pos) = __floats2half2_rn(o[nt][2] * inv1, o[nt][3] * inv1);
    }
}

// ---------------- host launch ------------------------------------------------
extern "C" void kernel_launch(void* const* d_in, const int* in_sizes, int n_in,
                              void* d_out, int out_size) {
    const float* x      = (const float*)d_in[0];
    const float* a      = (const float*)d_in[1];
    const float* gx     = (const float*)d_in[2];
    const float* ga     = (const float*)d_in[3];
    const float* Wq_x   = (const float*)d_in[4];
    const float* Wkv_x  = (const float*)d_in[5];
    const float* Wq_a   = (const float*)d_in[6];
    const float* Wkv_a  = (const float*)d_in[7];
    const float* Wout_x = (const float*)d_in[8];
    const float* bout_x = (const float*)d_in[9];
    const float* Wout_a = (const float*)d_in[10];
    const float* bout_a = (const float*)d_in[11];
    float* out = (float*)d_out;

    __half *sx, *sa, *qh, *kh, *vh, *oh;
    __half *wqx, *wkvx, *wqa, *wkva, *woutx, *wouta;
    float *qrx, *qra, *kvx, *kva;
    cudaGetSymbolAddress((void**)&sx,  g_sx);
    cudaGetSymbolAddress((void**)&sa,  g_sa);
    cudaGetSymbolAddress((void**)&qrx, g_qraw_x);
    cudaGetSymbolAddress((void**)&qra, g_qraw_a);
    cudaGetSymbolAddress((void**)&kvx, g_kvraw_x);
    cudaGetSymbolAddress((void**)&kva, g_kvraw_a);
    cudaGetSymbolAddress((void**)&qh,  g_q);
    cudaGetSymbolAddress((void**)&kh,  g_k);
    cudaGetSymbolAddress((void**)&vh,  g_v);
    cudaGetSymbolAddress((void**)&oh,  g_o);
    cudaGetSymbolAddress((void**)&wqx,   g_wq_x);
    cudaGetSymbolAddress((void**)&wkvx,  g_wkv_x);
    cudaGetSymbolAddress((void**)&wqa,   g_wq_a);
    cudaGetSymbolAddress((void**)&wkva,  g_wkv_a);
    cudaGetSymbolAddress((void**)&woutx, g_wout_x);
    cudaGetSymbolAddress((void**)&wouta, g_wout_a);

    const int GEMM_SMEM = (3 * GSTAGE + 3 * BSTAGE) * 2;             // 62208
    const int ATTN_SMEM = (2 * 128 * AKSTR + 2 * 32 * AVSTR) * 2;    // 83968
    cudaFuncSetAttribute(gemm_fp16,
                         cudaFuncAttributeMaxDynamicSharedMemorySize, GEMM_SMEM);
    cudaFuncSetAttribute(attn_tc_kernel,
                         cudaFuncAttributeMaxDynamicSharedMemorySize, ATTN_SMEM);

    // 0) prep: weights -> fp16 octrow, rope tables
    int prep_items = 1310720 + NSEQ * 32 / 2;
    prep_kernel<<<(prep_items + 255) / 256, 256>>>(Wq_x, Wkv_x, Wq_a, Wkv_a, Wout_x, Wout_a);

    // 1) RMSNorm -> fp16 perm'd
    rmsnorm_kernel<<<dim3(NSEQ, 2), 256>>>(x, a, gx, ga, sx, sa);

    // 2) QKV GEMMs: fused Wq (8 n-blocks) + Wkv (4 n-blocks), z = stream
    gemm_fp16<<<dim3(12, 16, 2), 256, GEMM_SMEM>>>(
        sx, sa, wqx, wqa, qrx, qra, 1024,
        wkvx, wkva, kvx, kva, 512, 8, nullptr, nullptr, NSEQ, 1024);

    // 3) RoPE + scatter: a -> joint [0,2048), x -> [2048,4096)
    int rope_blocks = (NSEQ * 576 + 255) / 256;
    rope_scatter_kernel<<<dim3(rope_blocks, 2), 256>>>(qra, qrx, kva, kvx);

    // 4) Joint attention
    attn_tc_kernel<<<dim3(NTOT / 32, KVHH), 256, ATTN_SMEM>>>(qh, kh, vh, oh);

    // 5) Output projections
    gemm_fp16<<<dim3(8, 16, 2), 256, GEMM_SMEM>>>(
        oh + (size_t)NSEQ * DIMV, oh, woutx, wouta,
        out, out + (size_t)NSEQ * DIMV, 1024,
        woutx, wouta, out, out + (size_t)NSEQ * DIMV, 1024, 8,
        bout_x, bout_a, NSEQ, 1024);
    (void)in_sizes; (void)n_in; (void)out_size;
}

// round 17
// speedup vs baseline: 1.0140x; 1.0140x over previous
#include <cuda_runtime.h>
#include <cuda_fp16.h>
#include <math.h>

#define NSEQ 2048
#define NTOT 4096
#define DIMV 1024
#define HH   16
#define KVHH 4

// ---------------- scratch ---------------------------------------------------
__device__ __half g_sx[NSEQ * DIMV];        // rmsnorm out, perm'd k-dim
__device__ __half g_sa[NSEQ * DIMV];
__device__ float  g_qraw_x[NSEQ * 1024];
__device__ float  g_qraw_a[NSEQ * 1024];
__device__ float  g_kvraw_x[NSEQ * 512];
__device__ float  g_kvraw_a[NSEQ * 512];
__device__ __half g_q[HH * NTOT * 64];      // pair-packed frag layout
__device__ __half g_k[KVHH * NTOT * 64];    // pair-packed frag layout
__device__ __half g_v[KVHH * NTOT * 64];    // pair-packed octrow layout
__device__ __half g_o[NTOT * DIMV];         // attention out, perm'd k-dim
__device__ float  g_tabc[NSEQ * 32];
__device__ float  g_tabs[NSEQ * 32];
// weights in fp16 octrow layout
__device__ __half g_wq_x[1024 * 1024];
__device__ __half g_wkv_x[1024 * 512];
__device__ __half g_wq_a[1024 * 1024];
__device__ __half g_wkv_a[1024 * 512];
__device__ __half g_wout_x[1024 * 1024];
__device__ __half g_wout_a[1024 * 1024];

// ---------------- helpers ----------------------------------------------------
__device__ __host__ __forceinline__ int perm16(int e) {
    return ((e & 7) >> 1) * 4 + ((e >> 3) << 1) + (e & 1);
}
// pair-packed Q/K row position
__device__ __forceinline__ int qk_pos(int d) {
    int ks = d >> 4, e = d & 15;
    return (ks >> 1) * 32 + ((e & 7) >> 1) * 8 + (ks & 1) * 4
         + ((e >> 3) << 1) + (e & 1);
}
__device__ __forceinline__ unsigned ex2h2(__half2 h) {
    unsigned u = *(unsigned*)&h, y;
    asm("ex2.approx.f16x2 %0, %1;" : "=r"(y) : "r"(u));
    return y;
}
__device__ __forceinline__ void mma16(float* c, const unsigned* a, unsigned b0, unsigned b1) {
    asm volatile(
        "mma.sync.aligned.m16n8k16.row.col.f32.f16.f16.f32 "
        "{%0,%1,%2,%3},{%4,%5,%6,%7},{%8,%9},{%0,%1,%2,%3};"
        : "+f"(c[0]), "+f"(c[1]), "+f"(c[2]), "+f"(c[3])
        : "r"(a[0]), "r"(a[1]), "r"(a[2]), "r"(a[3]), "r"(b0), "r"(b1));
}
__device__ __forceinline__ void cpa(void* dst, const void* src) {
    unsigned d = (unsigned)__cvta_generic_to_shared(dst);
    asm volatile("cp.async.cg.shared.global [%0], [%1], 16;" :: "r"(d), "l"(src));
}
#define CP_COMMIT() asm volatile("cp.async.commit_group;" ::)
#define CP_WAIT0()  asm volatile("cp.async.wait_group 0;" ::)
#define CP_WAIT1()  asm volatile("cp.async.wait_group 1;" ::)

#define PREP_BLOCKS 5248   // ceil((1310720 + 32768) / 256)

// ---------------- fused prep (weights->fp16 octrow + rope table) + RMSNorm ---
__global__ void prep_rms_kernel(
    const float* __restrict__ wqx_s, const float* __restrict__ wkvx_s,
    const float* __restrict__ wqa_s, const float* __restrict__ wkva_s,
    const float* __restrict__ woutx_s, const float* __restrict__ wouta_s,
    const float* __restrict__ x0, const float* __restrict__ x1,
    const float* __restrict__ g0, const float* __restrict__ g1,
    __half* __restrict__ o0, __half* __restrict__ o1) {
    __shared__ float red[8];
    if (blockIdx.x < PREP_BLOCKS) {
        // ---- prep body (identical to the 287.2us prep_kernel) ----
        int i = blockIdx.x * 256 + threadIdx.x;
        const int I1 = 262144, I2 = I1 + 131072, I3 = I2 + 262144;
        const int I4 = I3 + 131072, I5 = I4 + 262144, I6 = I5 + 262144;  // 1310720
        if (i < I6) {
            const float* src; __half* dst; int off, N;
            if (i < I1)      { src = wqx_s;   dst = g_wq_x;   off = i;      N = 1024; }
            else if (i < I2) { src = wkvx_s;  dst = g_wkv_x;  off = i - I1; N = 512; }
            else if (i < I3) { src = wqa_s;   dst = g_wq_a;   off = i - I2; N = 1024; }
            else if (i < I4) { src = wkva_s;  dst = g_wkv_a;  off = i - I3; N = 512; }
            else if (i < I5) { src = woutx_s; dst = g_wout_x; off = i - I4; N = 1024; }
            else             { src = wouta_s; dst = g_wout_a; off = i - I5; N = 1024; }
            int nh = N >> 1;
            int k = (off / nh) * 2, n = (off % nh) * 2;
            float2 r0 = *(const float2*)(src + (size_t)k * N + n);
            float2 r1 = *(const float2*)(src + (size_t)(k + 1) * N + n);
            int J = k >> 4, e = k & 15;
            int qr = (e & 7) >> 1, s = (e >> 3) << 1;   // e even
            size_t base = (size_t)J * 16 * N + (size_t)qr * 4 * N + (size_t)n * 4 + s;
            *(__half2*)(dst + base)     = __floats2half2_rn(r0.x, r1.x);
            *(__half2*)(dst + base + 4) = __floats2half2_rn(r0.y, r1.y);
        } else if (i < I6 + NSEQ * 32 / 2) {
            int j = (i - I6) * 2;
            #pragma unroll
            for (int u = 0; u < 2; u++) {
                int idx = j + u;
                int t = idx >> 5, fi = idx & 31;
                float invf = powf(10000.0f, -(float)fi * (1.0f / 32.0f));
                float ang = (2.0f * (float)t) * invf;
                float sn, cs;
                sincosf(ang, &sn, &cs);
                g_tabc[idx] = cs;
                g_tabs[idx] = sn;
            }
        }
    } else {
        // ---- rmsnorm body (identical logic; row/stream from offset index) ----
        int b = blockIdx.x - PREP_BLOCKS;     // 0..4095
        int row = b & (NSEQ - 1);
        int str = b >> 11;
        const float* x = str ? x1 : x0;
        const float* g = str ? g1 : g0;
        __half* out = str ? o1 : o0;
        const float4* xr = (const float4*)(x + (size_t)row * DIMV);
        float4 v = xr[threadIdx.x];
        float ss = v.x * v.x + v.y * v.y + v.z * v.z + v.w * v.w;
        #pragma unroll
        for (int m = 16; m; m >>= 1) ss += __shfl_xor_sync(0xffffffffu, ss, m);
        if ((threadIdx.x & 31) == 0) red[threadIdx.x >> 5] = ss;
        __syncthreads();
        if (threadIdx.x < 8) {
            float t = red[threadIdx.x];
            #pragma unroll
            for (int m = 4; m; m >>= 1) t += __shfl_xor_sync(0xffu, t, m);
            if (threadIdx.x == 0) red[0] = t;
        }
        __syncthreads();
        float rs = rsqrtf(red[0] * (1.0f / (float)DIMV) + 1e-6f);
        float4 gv = ((const float4*)g)[threadIdx.x];
        int d0 = threadIdx.x * 4;
        int base = d0 & ~15, e0 = d0 & 15;
        __half* outrow = out + (size_t)row * DIMV + base;
        *(__half2*)(outrow + perm16(e0))     = __floats2half2_rn(v.x * rs * gv.x, v.y * rs * gv.y);
        *(__half2*)(outrow + perm16(e0 + 2)) = __floats2half2_rn(v.z * rs * gv.z, v.w * rs * gv.w);
    }
}

// ---------------- fp16 GEMM: 128x128, 3-stage cp.async, 1 sync/iter ----------
#define GASTR 48
#define GBSTR 528
#define GSTAGE (128 * GASTR)
#define BSTAGE (8 * GBSTR)
__global__ void __launch_bounds__(256, 2) gemm_fp16(
    const __half* __restrict__ Az0, const __half* __restrict__ Az1,
    const __half* __restrict__ Bq0, const __half* __restrict__ Bq1,
    float* __restrict__ Cq0, float* __restrict__ Cq1, int N1,
    const __half* __restrict__ Bk0, const __half* __restrict__ Bk1,
    float* __restrict__ Ck0, float* __restrict__ Ck1, int N2,
    int split,
    const float* __restrict__ bias0, const float* __restrict__ bias1,
    int M, int K) {
    const __half* A = blockIdx.z ? Az1 : Az0;
    const __half* B;
    float* C;
    const float* bias = blockIdx.z ? bias1 : bias0;
    int N, n0;
    if ((int)blockIdx.x < split) {
        B = blockIdx.z ? Bq1 : Bq0; C = blockIdx.z ? Cq1 : Cq0;
        N = N1; n0 = blockIdx.x * 128;
    } else {
        B = blockIdx.z ? Bk1 : Bk0; C = blockIdx.z ? Ck1 : Ck0;
        N = N2; n0 = (blockIdx.x - split) * 128;
    }
    extern __shared__ __half smh[];
    __half* As = smh;                       // [3][128*48]
    __half* Bs = smh + 3 * GSTAGE;          // [3][8*528]
    int m0 = blockIdx.y * 128;
    int tid = threadIdx.x;
    int warp = tid >> 5, lane = tid & 31;
    int wm = warp >> 2, wn = warp & 3;
    int g = lane >> 2, qr = lane & 3;

    float acc[4][4][4];
    #pragma unroll
    for (int mt = 0; mt < 4; mt++)
        #pragma unroll
        for (int nt = 0; nt < 4; nt++)
            #pragma unroll
            for (int i = 0; i < 4; i++) acc[mt][nt][i] = 0.0f;

    auto stage = [&](int k0, int buf) {
        __half* ab = As + buf * GSTAGE;
        __half* bb = Bs + buf * BSTAGE;
        #pragma unroll
        for (int i = 0; i < 2; i++) {
            int f = tid + i * 256;
            int r = f >> 2, c = f & 3;
            cpa(ab + r * GASTR + c * 8, A + (size_t)(m0 + r) * K + k0 + c * 8);
        }
        #pragma unroll
        for (int i = 0; i < 2; i++) {
            int f = tid + i * 256;
            int orow = f >> 6, c = f & 63;
            int J = (k0 >> 4) + (orow >> 2);
            cpa(bb + orow * GBSTR + c * 8,
                B + ((size_t)J * 16 + (orow & 3) * 4) * N + (size_t)n0 * 4 + c * 8);
        }
    };

    int nk = K >> 5;                         // 32
    stage(0, 0);
    CP_COMMIT();
    stage(32, 1);
    CP_COMMIT();
    int bcur = 0, bnxt2 = 2;
    for (int it = 0; it < nk; it++) {
        CP_WAIT1();
        __syncthreads();
        if (it + 2 < nk) {
            stage((it + 2) << 5, bnxt2);
            CP_COMMIT();
        }
        const __half* as = As + bcur * GSTAGE;
        const __half* bs = Bs + bcur * BSTAGE;
        #pragma unroll
        for (int ks = 0; ks < 2; ks++) {
            unsigned a[4][4], b[4][2];
            #pragma unroll
            for (int mt = 0; mt < 4; mt++) {
                int rb = wm * 64 + mt * 16;
                uint2 lo = *(const uint2*)(as + (rb + g) * GASTR + ks * 16 + qr * 4);
                uint2 hi = *(const uint2*)(as + (rb + g + 8) * GASTR + ks * 16 + qr * 4);
                a[mt][0] = lo.x; a[mt][1] = hi.x; a[mt][2] = lo.y; a[mt][3] = hi.y;
            }
            #pragma unroll
            for (int nt = 0; nt < 4; nt++) {
                uint2 bv = *(const uint2*)(bs + (ks * 4 + qr) * GBSTR + (wn * 32 + nt * 8 + g) * 4);
                b[nt][0] = bv.x; b[nt][1] = bv.y;
            }
            #pragma unroll
            for (int mt = 0; mt < 4; mt++)
                #pragma unroll
                for (int nt = 0; nt < 4; nt++)
                    mma16(acc[mt][nt], a[mt], b[nt][0], b[nt][1]);
        }
        bcur = (bcur == 2) ? 0 : bcur + 1;
        bnxt2 = (bnxt2 == 2) ? 0 : bnxt2 + 1;
    }

    #pragma unroll
    for (int mt = 0; mt < 4; mt++) {
        int row0 = m0 + wm * 64 + mt * 16 + g;
        #pragma unroll
        for (int nt = 0; nt < 4; nt++) {
            int col = n0 + wn * 32 + nt * 8 + qr * 2;
            float bx = 0.0f, by = 0.0f;
            if (bias) { float2 bb = *(const float2*)(bias + col); bx = bb.x; by = bb.y; }
            float2 lo = {acc[mt][nt][0] + bx, acc[mt][nt][1] + by};
            float2 hi = {acc[mt][nt][2] + bx, acc[mt][nt][3] + by};
            *(float2*)(C + (size_t)row0 * N + col) = lo;
            *(float2*)(C + (size_t)(row0 + 8) * N + col) = hi;
        }
    }
}

// ---------------- RoPE + scatter -> pair-packed fp16 layouts -----------------
__global__ void rope_scatter_kernel(const float* __restrict__ qraw_a, const float* __restrict__ qraw_x,
                                    const float* __restrict__ kvraw_a, const float* __restrict__ kvraw_x) {
    const float* qraw = blockIdx.y ? qraw_x : qraw_a;
    const float* kvraw = blockIdx.y ? kvraw_x : kvraw_a;
    int toff = blockIdx.y ? NSEQ : 0;
    int idx = blockIdx.x * 256 + threadIdx.x;
    if (idx >= NSEQ * 576) return;
    int t = idx / 576;
    int c = idx % 576;
    const float QSC = 0.015625f * 1.44269504088896f;  // 1/DH * log2(e)

    if (c < 320) {
        bool isQ = c < 256;
        int cc = isQ ? c : c - 256;
        int h = cc >> 4;
        int d = (cc & 15) * 2;        // d in [0,32), even
        const float* base = isQ ? (qraw + t * 1024 + h * 64)
                                : (kvraw + t * 512 + h * 64);
        float2 lo = *(const float2*)(base + d);
        float2 hi = *(const float2*)(base + d + 32);
        float c0 = g_tabc[t * 32 + d], c1 = g_tabc[t * 32 + d + 1];
        float s0 = g_tabs[t * 32 + d], s1 = g_tabs[t * 32 + d + 1];
        float lo0 = lo.x * c0 - hi.x * s0, lo1 = lo.y * c1 - hi.y * s1;
        float hi0 = hi.x * c0 + lo.x * s0, hi1 = hi.y * c1 + lo.y * s1;
        __half* dst;
        if (isQ) {
            lo0 *= QSC; lo1 *= QSC; hi0 *= QSC; hi1 *= QSC;
            dst = g_q + ((size_t)h * NTOT + toff + t) * 64;
        } else {
            dst = g_k + ((size_t)h * NTOT + toff + t) * 64;
        }
        *(__half2*)(dst + qk_pos(d))      = __floats2half2_rn(lo0, lo1);
        *(__half2*)(dst + qk_pos(d + 32)) = __floats2half2_rn(hi0, hi1);
    } else {
        int cc = c - 320;
        int kh = cc >> 6, d = cc & 63;
        int tj = toff + t;
        int r = tj & 63;
        int j = r >> 4, e = r & 15;
        int qrv = (e & 7) >> 1, sv = ((e >> 3) << 1) | (e & 1);
        int nt = d >> 3, gg = d & 7;
        size_t pos = (size_t)kh * NTOT * 64 + (size_t)(tj >> 6) * 4096
                   + (size_t)(j * 4 + qrv) * 256
                   + (nt >> 1) * 64 + gg * 8 + (nt & 1) * 4 + sv;
        g_v[pos] = __float2half_rn(kvraw[t * 512 + 256 + kh * 64 + d]);
    }
}

// ---------------- Flash attention: pair-packed LDS.128, 1 sync/iter ----------
#define AKSTR 96
#define AVSTR 272
__global__ void __launch_bounds__(256, 2) attn_tc_kernel(
    const __half* __restrict__ Q, const __half* __restrict__ K,
    const __half* __restrict__ V, __half* __restrict__ O) {
    extern __shared__ __half smh[];
    __half* Ks = smh;                        // [2][128*96]
    __half* Vs = smh + 2 * 128 * AKSTR;      // [2][32*272]

    int kh = blockIdx.y;
    int q0 = blockIdx.x * 32;
    int tid = threadIdx.x;
    int warp = tid >> 5, lane = tid & 31;
    int g = lane >> 2, qr = lane & 3;
    int hq = kh + (warp >> 1) * 4;
    int qrow0 = q0 + (warp & 1) * 16;

    const __half* Kg = K + (size_t)kh * NTOT * 64;
    const __half* Vg = V + (size_t)kh * NTOT * 64;

    auto stage = [&](int kt, int buf) {
        const __half* Kt = Kg + (size_t)kt * 8192;
        const __half* Vt = Vg + (size_t)kt * 8192;
        __half* kb = Ks + buf * 128 * AKSTR;
        __half* vb = Vs + buf * 32 * AVSTR;
        #pragma unroll
        for (int i = 0; i < 4; i++) {
            int f = tid + i * 256;
            int r = f >> 3, c = f & 7;
            cpa(kb + r * AKSTR + c * 8, Kt + r * 64 + c * 8);
        }
        #pragma unroll
        for (int i = 0; i < 4; i++) {
            int f = tid + i * 256;
            int orow = f >> 5, c = f & 31;
            cpa(vb + orow * AVSTR + c * 8, Vt + orow * 256 + c * 8);
        }
    };

    stage(0, 0);
    CP_COMMIT();

    unsigned qa[4][4];
    {
        const __half* Qg = Q + ((size_t)hq * NTOT + qrow0) * 64;
        #pragma unroll
        for (int p = 0; p < 2; p++) {
            uint4 Ug = *(const uint4*)(Qg + g * 64 + p * 32 + qr * 8);
            uint4 Uh = *(const uint4*)(Qg + (g + 8) * 64 + p * 32 + qr * 8);
            qa[2 * p][0] = Ug.x;     qa[2 * p][2] = Ug.y;
            qa[2 * p + 1][0] = Ug.z; qa[2 * p + 1][2] = Ug.w;
            qa[2 * p][1] = Uh.x;     qa[2 * p][3] = Uh.y;
            qa[2 * p + 1][1] = Uh.z; qa[2 * p + 1][3] = Uh.w;
        }
    }

    float o[8][4];
    #pragma unroll
    for (int nt = 0; nt < 8; nt++)
        #pragma unroll
        for (int i = 0; i < 4; i++) o[nt][i] = 0.0f;
    float lacc[4] = {0.0f, 0.0f, 0.0f, 0.0f};
    const unsigned ONES2 = 0x3C003C00u;
    const __half2 HCLAMP = __floats2half2_rn(15.0f, 15.0f);

    auto compute64 = [&](const __half* kb, const __half* vb) {
        float sacc[8][4];
        #pragma unroll
        for (int nt = 0; nt < 8; nt++) {
            #pragma unroll
            for (int i = 0; i < 4; i++) sacc[nt][i] = 0.0f;
            const __half* krow = kb + (nt * 8 + g) * AKSTR + qr * 8;
            #pragma unroll
            for (int p = 0; p < 2; p++) {
                uint4 kk = *(const uint4*)(krow + p * 32);
                mma16(sacc[nt], qa[2 * p],     kk.x, kk.y);
                mma16(sacc[nt], qa[2 * p + 1], kk.z, kk.w);
            }
        }
        #pragma unroll
        for (int j = 0; j < 4; j++) {
            unsigned pa[4];
            #pragma unroll
            for (int t = 0; t < 2; t++) {
                int nt = 2 * j + t;
                __half2 h0 = __floats2half2_rn(sacc[nt][0], sacc[nt][1]);
                __half2 h1 = __floats2half2_rn(sacc[nt][2], sacc[nt][3]);
                h0 = __hmin2(h0, HCLAMP);
                h1 = __hmin2(h1, HCLAMP);
                pa[2 * t]     = ex2h2(h0);
                pa[2 * t + 1] = ex2h2(h1);
            }
            mma16(lacc, pa, ONES2, ONES2);
            const __half* vrow = vb + (j * 4 + qr) * AVSTR + g * 8;
            #pragma unroll
            for (int nt2 = 0; nt2 < 4; nt2++) {
                uint4 vv = *(const uint4*)(vrow + nt2 * 64);
                mma16(o[2 * nt2], pa, vv.x, vv.y);
                mma16(o[2 * nt2 + 1], pa, vv.z, vv.w);
            }
        }
    };

    for (int kt = 0; kt < NTOT / 128; kt++) {
        CP_WAIT0();
        __syncthreads();
        if (kt + 1 < NTOT / 128) {
            stage(kt + 1, (kt + 1) & 1);
            CP_COMMIT();
        }
        const __half* kb = Ks + (kt & 1) * 128 * AKSTR;
        const __half* vb = Vs + (kt & 1) * 32 * AVSTR;
        compute64(kb, vb);
        compute64(kb + 64 * AKSTR, vb + 16 * AVSTR);
    }

    float inv0 = 1.0f / lacc[0], inv1 = 1.0f / lacc[2];
    int t0 = qrow0 + g;
    __half* Ob = O + (size_t)t0 * DIMV + hq * 64;
    #pragma unroll
    for (int nt = 0; nt < 8; nt++) {
        int c = nt * 8 + qr * 2;
        int pos = (c & ~15) | perm16(c & 15);
        *(__half2*)(Ob + pos) = __floats2half2_rn(o[nt][0] * inv0, o[nt][1] * inv0);
        *(__half2*)(Ob + (size_t)8 * DIMV + pos) = __floats2half2_rn(o[nt][2] * inv1, o[nt][3] * inv1);
    }
}

// ---------------- host launch ------------------------------------------------
extern "C" void kernel_launch(void* const* d_in, const int* in_sizes, int n_in,
                              void* d_out, int out_size) {
    const float* x      = (const float*)d_in[0];
    const float* a      = (const float*)d_in[1];
    const float* gx     = (const float*)d_in[2];
    const float* ga     = (const float*)d_in[3];
    const float* Wq_x   = (const float*)d_in[4];
    const float* Wkv_x  = (const float*)d_in[5];
    const float* Wq_a   = (const float*)d_in[6];
    const float* Wkv_a  = (const float*)d_in[7];
    const float* Wout_x = (const float*)d_in[8];
    const float* bout_x = (const float*)d_in[9];
    const float* Wout_a = (const float*)d_in[10];
    const float* bout_a = (const float*)d_in[11];
    float* out = (float*)d_out;

    __half *sx, *sa, *qh, *kh, *vh, *oh;
    __half *wqx, *wkvx, *wqa, *wkva, *woutx, *wouta;
    float *qrx, *qra, *kvx, *kva;
    cudaGetSymbolAddress((void**)&sx,  g_sx);
    cudaGetSymbolAddress((void**)&sa,  g_sa);
    cudaGetSymbolAddress((void**)&qrx, g_qraw_x);
    cudaGetSymbolAddress((void**)&qra, g_qraw_a);
    cudaGetSymbolAddress((void**)&kvx, g_kvraw_x);
    cudaGetSymbolAddress((void**)&kva, g_kvraw_a);
    cudaGetSymbolAddress((void**)&qh,  g_q);
    cudaGetSymbolAddress((void**)&kh,  g_k);
    cudaGetSymbolAddress((void**)&vh,  g_v);
    cudaGetSymbolAddress((void**)&oh,  g_o);
    cudaGetSymbolAddress((void**)&wqx,   g_wq_x);
    cudaGetSymbolAddress((void**)&wkvx,  g_wkv_x);
    cudaGetSymbolAddress((void**)&wqa,   g_wq_a);
    cudaGetSymbolAddress((void**)&wkva,  g_wkv_a);
    cudaGetSymbolAddress((void**)&woutx, g_wout_x);
    cudaGetSymbolAddress((void**)&wouta, g_wout_a);

    const int GEMM_SMEM = (3 * GSTAGE + 3 * BSTAGE) * 2;             // 62208
    const int ATTN_SMEM = (2 * 128 * AKSTR + 2 * 32 * AVSTR) * 2;    // 83968
    cudaFuncSetAttribute(gemm_fp16,
                         cudaFuncAttributeMaxDynamicSharedMemorySize, GEMM_SMEM);
    cudaFuncSetAttribute(attn_tc_kernel,
                         cudaFuncAttributeMaxDynamicSharedMemorySize, ATTN_SMEM);

    // 0+1) fused prep (weights->fp16 octrow, rope tables) + RMSNorm
    prep_rms_kernel<<<PREP_BLOCKS + 2 * NSEQ, 256>>>(
        Wq_x, Wkv_x, Wq_a, Wkv_a, Wout_x, Wout_a,
        x, a, gx, ga, sx, sa);

    // 2) QKV GEMMs: fused Wq (8 n-blocks) + Wkv (4 n-blocks), z = stream
    gemm_fp16<<<dim3(12, 16, 2), 256, GEMM_SMEM>>>(
        sx, sa, wqx, wqa, qrx, qra, 1024,
        wkvx, wkva, kvx, kva, 512, 8, nullptr, nullptr, NSEQ, 1024);

    // 3) RoPE + scatter: a -> joint [0,2048), x -> [2048,4096)
    int rope_blocks = (NSEQ * 576 + 255) / 256;
    rope_scatter_kernel<<<dim3(rope_blocks, 2), 256>>>(qra, qrx, kva, kvx);

    // 4) Joint attention
    attn_tc_kernel<<<dim3(NTOT / 32, KVHH), 256, ATTN_SMEM>>>(qh, kh, vh, oh);

    // 5) Output projections
    gemm_fp16<<<dim3(8, 16, 2), 256, GEMM_SMEM>>>(
        oh + (size_t)NSEQ * DIMV, oh, woutx, wouta,
        out, out + (size_t)NSEQ * DIMV, 1024,
        woutx, wouta, out, out + (size_t)NSEQ * DIMV, 1024, 8,
        bout_x, bout_a, NSEQ, 1024);
    (void)in_sizes; (void)n_in; (void)out_size;
}